// round 8
// baseline (speedup 1.0000x reference)
#include <cuda_runtime.h>
#include <cuda_fp16.h>
#include <mma.h>
#include <cstdint>
using namespace nvcuda;

#define N_NODES 100000
#define N_EDGES 1600000
#define NPAD    100352   // multiple of 256

__device__ int   g_is64;
__device__ int   g_cnt[N_NODES];
__device__ int   g_fill[N_NODES];
__device__ float g_dis[N_NODES];
__device__ int   g_rowptr[N_NODES + 1];
__device__ int   g_incl[256];        // chained-scan inclusive totals (+1 flag); zeroed each run
__device__ int   g_colsrc[N_EDGES];
__device__ __align__(16) __half g_xh  [(size_t)NPAD * 32];
__device__ __align__(16) __half g_s32h[(size_t)NPAD * 32];
__device__ __align__(16) __half g_h16 [(size_t)NPAD * 128];
__device__ __align__(16) __half g_hB  [(size_t)NPAD * 128];
__device__ __align__(16) __half g_hA  [(size_t)NPAD * 128];
__device__ __align__(16) __half g_s3h [(size_t)NPAD * 32];

// ---- prep: zero counts & scan flags, convert x->fp16, detect edge dtype ----
__global__ void k_prep(const float* __restrict__ x, const int* __restrict__ w,
                       int N, int E) {
    int i = blockIdx.x * blockDim.x + threadIdx.x;
    if (i < N) g_cnt[i] = 0;
    if (i < 256) g_incl[i] = 0;
    if (i < N * 32) g_xh[i] = __float2half(x[i]);
    if (blockIdx.x == 0) {
        __shared__ int any;
        if (threadIdx.x == 0) any = 0;
        __syncthreads();
        int n = min(2048, E);
        int local = 0;
        for (int j = threadIdx.x; j < n; j += blockDim.x) local |= w[2 * j + 1];
        if (local) atomicOr(&any, 1);
        __syncthreads();
        if (threadIdx.x == 0) g_is64 = (any == 0) ? 1 : 0;
    }
}

__device__ __forceinline__ int edge_at(const void* ed, size_t idx) {
    return g_is64 ? (int)((const long long*)ed)[idx] : ((const int*)ed)[idx];
}

__global__ void k_count(const void* __restrict__ edges, int E, int N) {
    int e = blockIdx.x * blockDim.x + threadIdx.x;
    if (e >= E) return;
    int d = edge_at(edges, (size_t)E + e);
    if ((unsigned)d >= (unsigned)N) return;
    atomicAdd(&g_cnt[d], 1);
}

// ---- single-pass chained scan: rowptr (exclusive), dis, fill init — one launch ----
// 98 blocks of 1024; all co-resident on 148 SMs => spin-wait chain is safe.
__global__ __launch_bounds__(1024) void scan_onepass(int N, int nb) {
    __shared__ int sm[1024];
    __shared__ int s_excl;
    const int tid = threadIdx.x;
    const int idx = blockIdx.x * 1024 + tid;
    int c = (idx < N) ? g_cnt[idx] : 0;
    if (idx < N) { g_dis[idx] = rsqrtf((float)(c + 1)); g_fill[idx] = 0; }
    sm[tid] = c;
    __syncthreads();
    // Hillis-Steele inclusive scan
    for (int off = 1; off < 1024; off <<= 1) {
        int t = (tid >= off) ? sm[tid - off] : 0;
        __syncthreads();
        sm[tid] += t;
        __syncthreads();
    }
    int tilesum = sm[1023];
    if (tid == 0) {
        int excl = 0;
        if (blockIdx.x > 0) {
            int v;
            do { v = atomicAdd(&g_incl[blockIdx.x - 1], 0); } while (v == 0);
            excl = v - 1;
        }
        s_excl = excl;
        atomicExch(&g_incl[blockIdx.x], excl + tilesum + 1);  // +1 = "published" flag
    }
    __syncthreads();
    const int excl = s_excl;
    if (idx < N) g_rowptr[idx] = excl + sm[tid] - c;          // exclusive
    if (blockIdx.x == nb - 1 && tid == 0) g_rowptr[N] = excl + tilesum;
}

__global__ void fill_csr(const void* __restrict__ edges, int E, int N) {
    int e = blockIdx.x * blockDim.x + threadIdx.x;
    if (e >= E) return;
    int s = edge_at(edges, e);
    int d = edge_at(edges, (size_t)E + e);
    if ((unsigned)s >= (unsigned)N || (unsigned)d >= (unsigned)N) return;
    int pos = g_rowptr[d] + atomicAdd(&g_fill[d], 1);
    g_colsrc[pos] = s;
}

// ---------------- tensor-core GEMM: Y[N,NOUT] = A[N,K](fp16) @ W(fp32->fp16) ----
template <int K, int NOUT, bool EPI>
__global__ __launch_bounds__(256) void wgemm(
    const __half* __restrict__ A, const float* __restrict__ Wf,
    const float* __restrict__ Bias, __half* __restrict__ Y)
{
    constexpr int WN = (NOUT == 128) ? 2 : 1;
    constexpr int WM = 8 / WN;
    constexpr int NFRAG = NOUT / (WN * 16);
    constexpr int MFRAG = 2;
    constexpr int MBLK = WM * MFRAG * 16;
    constexpr int LDA = K + 8;
    constexpr int LDB = NOUT + 8;
    extern __shared__ __half smh[];
    __half* As = smh;
    __half* Bs = smh + MBLK * LDA;
    const int tid = threadIdx.x;
    const int row0 = blockIdx.x * MBLK;

    for (int i = tid; i < K * NOUT; i += 256) {
        int k = i / NOUT, n = i % NOUT;
        Bs[k * LDB + n] = __float2half(Wf[i]);
    }
    constexpr int CH = K / 8;
    for (int i = tid; i < MBLK * CH; i += 256) {
        int r = i / CH, ch = i % CH;
        uint4 v = *(const uint4*)&A[((size_t)(row0 + r)) * K + ch * 8];
        *(uint4*)&As[r * LDA + ch * 8] = v;
    }
    __syncthreads();

    const int wid = tid >> 5;
    const int wm = wid % WM, wn = wid / WM;
    const int mrow = wm * MFRAG * 16;
    const int ncol = wn * NFRAG * 16;

    wmma::fragment<wmma::accumulator, 16, 16, 16, float> acc[MFRAG][NFRAG];
#pragma unroll
    for (int m = 0; m < MFRAG; m++)
#pragma unroll
        for (int n = 0; n < NFRAG; n++) wmma::fill_fragment(acc[m][n], 0.f);

#pragma unroll
    for (int k = 0; k < K; k += 16) {
        wmma::fragment<wmma::matrix_a, 16, 16, 16, __half, wmma::row_major> af[MFRAG];
#pragma unroll
        for (int m = 0; m < MFRAG; m++)
            wmma::load_matrix_sync(af[m], As + (mrow + m * 16) * LDA + k, LDA);
        wmma::fragment<wmma::matrix_b, 16, 16, 16, __half, wmma::row_major> bf[NFRAG];
#pragma unroll
        for (int n = 0; n < NFRAG; n++)
            wmma::load_matrix_sync(bf[n], Bs + k * LDB + ncol + n * 16, LDB);
#pragma unroll
        for (int m = 0; m < MFRAG; m++)
#pragma unroll
            for (int n = 0; n < NFRAG; n++)
                wmma::mma_sync(acc[m][n], af[m], bf[n], acc[m][n]);
    }
    __syncthreads();

    float* stage = (float*)smh + wid * 272;
    const int lane = tid & 31;
    const int r = lane >> 1, c0 = (lane & 1) * 8;
#pragma unroll
    for (int m = 0; m < MFRAG; m++)
#pragma unroll
        for (int n = 0; n < NFRAG; n++) {
            wmma::store_matrix_sync(stage, acc[m][n], 16, wmma::mem_row_major);
            __syncwarp();
            int grow = row0 + mrow + m * 16 + r;
            int gcol = ncol + n * 16 + c0;
            __half h[8];
#pragma unroll
            for (int j = 0; j < 8; j++) {
                float v = stage[r * 16 + c0 + j];
                if constexpr (EPI) v = fmaxf(v + Bias[gcol + j], 0.f);
                h[j] = __float2half(v);
            }
            *(uint4*)&Y[(size_t)grow * NOUT + gcol] = *(uint4*)h;
            __syncwarp();
        }
}

// ---------------- agg F=32 ----------------
template <bool EPI, bool OUTF>
__global__ __launch_bounds__(256) void agg32_kernel(
    const __half* __restrict__ H, const float* __restrict__ B,
    __half* __restrict__ outh, float* __restrict__ outf, int N)
{
    int gw = (blockIdx.x * 256 + threadIdx.x) >> 5;
    int lane = threadIdx.x & 31;
    if (gw >= N) return;
    const float di = g_dis[gw];
    const int beg = g_rowptr[gw], end = g_rowptr[gw + 1];

    float acc = di * __half2float(H[(size_t)gw * 32 + lane]);
    int e = beg;
    for (; e + 4 <= end; e += 4) {
        int s0 = g_colsrc[e], s1 = g_colsrc[e + 1];
        int s2 = g_colsrc[e + 2], s3 = g_colsrc[e + 3];
        float w0 = g_dis[s0], w1 = g_dis[s1], w2 = g_dis[s2], w3 = g_dis[s3];
        float v0 = __half2float(H[(size_t)s0 * 32 + lane]);
        float v1 = __half2float(H[(size_t)s1 * 32 + lane]);
        float v2 = __half2float(H[(size_t)s2 * 32 + lane]);
        float v3 = __half2float(H[(size_t)s3 * 32 + lane]);
        acc = fmaf(w0, v0, acc);
        acc = fmaf(w1, v1, acc);
        acc = fmaf(w2, v2, acc);
        acc = fmaf(w3, v3, acc);
    }
    for (; e < end; e++) {
        int s = g_colsrc[e];
        acc = fmaf(g_dis[s], __half2float(H[(size_t)s * 32 + lane]), acc);
    }
    acc *= di;
    if constexpr (EPI) acc = fmaxf(acc + B[lane], 0.f);
    if constexpr (OUTF) outf[(size_t)gw * 32 + lane] = acc;
    else               outh[(size_t)gw * 32 + lane] = __float2half(acc);
}

// ---------------- agg F=128 ----------------
__device__ __forceinline__ float4 h4_to_f4(uint2 v) {
    __half2 a = *(__half2*)&v.x, b = *(__half2*)&v.y;
    float2 fa = __half22float2(a), fb = __half22float2(b);
    return make_float4(fa.x, fa.y, fb.x, fb.y);
}

__global__ __launch_bounds__(256) void agg128h_kernel(
    const __half* __restrict__ H, __half* __restrict__ out, int N)
{
    int gw = (blockIdx.x * 256 + threadIdx.x) >> 5;
    int lane = threadIdx.x & 31;
    if (gw >= N) return;
    const float di = g_dis[gw];
    const int beg = g_rowptr[gw], end = g_rowptr[gw + 1];

    float4 h0 = h4_to_f4(((const uint2*)(H + (size_t)gw * 128))[lane]);
    float4 acc = make_float4(di * h0.x, di * h0.y, di * h0.z, di * h0.w);
    int e = beg;
    for (; e + 4 <= end; e += 4) {
        int s0 = g_colsrc[e], s1 = g_colsrc[e + 1];
        int s2 = g_colsrc[e + 2], s3 = g_colsrc[e + 3];
        float w0 = g_dis[s0], w1 = g_dis[s1], w2 = g_dis[s2], w3 = g_dis[s3];
        float4 v0 = h4_to_f4(((const uint2*)(H + (size_t)s0 * 128))[lane]);
        float4 v1 = h4_to_f4(((const uint2*)(H + (size_t)s1 * 128))[lane]);
        float4 v2 = h4_to_f4(((const uint2*)(H + (size_t)s2 * 128))[lane]);
        float4 v3 = h4_to_f4(((const uint2*)(H + (size_t)s3 * 128))[lane]);
        acc.x = fmaf(w0, v0.x, acc.x); acc.y = fmaf(w0, v0.y, acc.y);
        acc.z = fmaf(w0, v0.z, acc.z); acc.w = fmaf(w0, v0.w, acc.w);
        acc.x = fmaf(w1, v1.x, acc.x); acc.y = fmaf(w1, v1.y, acc.y);
        acc.z = fmaf(w1, v1.z, acc.z); acc.w = fmaf(w1, v1.w, acc.w);
        acc.x = fmaf(w2, v2.x, acc.x); acc.y = fmaf(w2, v2.y, acc.y);
        acc.z = fmaf(w2, v2.z, acc.z); acc.w = fmaf(w2, v2.w, acc.w);
        acc.x = fmaf(w3, v3.x, acc.x); acc.y = fmaf(w3, v3.y, acc.y);
        acc.z = fmaf(w3, v3.z, acc.z); acc.w = fmaf(w3, v3.w, acc.w);
    }
    for (; e < end; e++) {
        int s = g_colsrc[e];
        float w = g_dis[s];
        float4 v = h4_to_f4(((const uint2*)(H + (size_t)s * 128))[lane]);
        acc.x = fmaf(w, v.x, acc.x); acc.y = fmaf(w, v.y, acc.y);
        acc.z = fmaf(w, v.z, acc.z); acc.w = fmaf(w, v.w, acc.w);
    }
    __half2 o01 = __floats2half2_rn(di * acc.x, di * acc.y);
    __half2 o23 = __floats2half2_rn(di * acc.z, di * acc.w);
    uint2 pk = make_uint2(*(unsigned*)&o01, *(unsigned*)&o23);
    ((uint2*)(out + (size_t)gw * 128))[lane] = pk;
}

extern "C" void kernel_launch(void* const* d_in, const int* in_sizes, int n_in,
                              void* d_out, int out_size) {
    const float* x  = (const float*)d_in[0];
    const void*  ed = d_in[1];
    const float* W1 = (const float*)d_in[2];
    const float* b1 = (const float*)d_in[3];
    const float* W2 = (const float*)d_in[4];
    const float* b2 = (const float*)d_in[5];
    const float* W3 = (const float*)d_in[6];
    const float* b3 = (const float*)d_in[7];
    float* out = (float*)d_out;

    const int N = in_sizes[0] / 32;
    const int E = in_sizes[1] / 2;
    const int nb = (N + 1023) / 1024;

    __half *xh, *s32h, *h16, *hB, *hA, *s3h;
    cudaGetSymbolAddress((void**)&xh,   g_xh);
    cudaGetSymbolAddress((void**)&s32h, g_s32h);
    cudaGetSymbolAddress((void**)&h16,  g_h16);
    cudaGetSymbolAddress((void**)&hB,   g_hB);
    cudaGetSymbolAddress((void**)&hA,   g_hA);
    cudaGetSymbolAddress((void**)&s3h,  g_s3h);

    const int eblk = (E + 255) / 256;
    const int ablk = (N * 32 + 255) / 256;
    const int pblk = (N * 32 + 255) / 256;

    const int sm1 = (128 * 40 + 32 * 136) * 2;
    const int sm2 = (128 * 136 + 128 * 136) * 2;
    const int sm3 = (256 * 136 + 128 * 40) * 2;
    cudaFuncSetAttribute(wgemm<32, 128, true>,  cudaFuncAttributeMaxDynamicSharedMemorySize, sm1);
    cudaFuncSetAttribute(wgemm<128, 128, true>, cudaFuncAttributeMaxDynamicSharedMemorySize, sm2);
    cudaFuncSetAttribute(wgemm<128, 32, false>, cudaFuncAttributeMaxDynamicSharedMemorySize, sm3);

    // CSR + norm build (4 launches)
    k_prep<<<pblk, 256>>>(x, (const int*)ed, N, E);
    k_count<<<eblk, 256>>>(ed, E, N);
    scan_onepass<<<nb, 1024>>>(N, nb);
    fill_csr<<<eblk, 256>>>(ed, E, N);

    // L1: relu(Agg(x) @ W1 + b1)
    agg32_kernel<false, false><<<ablk, 256>>>(xh, nullptr, s32h, nullptr, N);
    wgemm<32, 128, true><<<(N + 127) / 128, 256, sm1>>>(s32h, W1, b1, h16);

    // L2: relu(Agg(h1) @ W2 + b2)
    agg128h_kernel<<<ablk, 256>>>(h16, hB, N);
    wgemm<128, 128, true><<<(N + 127) / 128, 256, sm2>>>(hB, W2, b2, hA);

    // L3: relu(Agg(h2 @ W3) + b3)
    wgemm<128, 32, false><<<(N + 255) / 256, 256, sm3>>>(hA, W3, nullptr, s3h);
    agg32_kernel<true, true><<<ablk, 256>>>(s3h, b3, nullptr, out, N);
}

// round 12
// speedup vs baseline: 1.1656x; 1.1656x over previous
#include <cuda_runtime.h>
#include <cuda_fp16.h>
#include <mma.h>
#include <cstdint>
using namespace nvcuda;

#define N_NODES 100000
#define N_EDGES 1600000
#define NPAD    100352   // multiple of 256

__device__ int   g_cnt[N_NODES];     // zero at module load; re-zeroed in scan_write each run
__device__ int   g_fill[N_NODES];
__device__ float g_dis[N_NODES];
__device__ int   g_rowptr[N_NODES + 1];
__device__ int   g_bsum[256];
__device__ int   g_bofs[256];
__device__ int   g_colsrc[N_EDGES];
__device__ __align__(16) __half g_xh  [(size_t)NPAD * 32];
__device__ __align__(16) __half g_s32h[(size_t)NPAD * 32];
__device__ __align__(16) __half g_h16 [(size_t)NPAD * 128];
__device__ __align__(16) __half g_hB  [(size_t)NPAD * 128];
__device__ __align__(16) __half g_hA  [(size_t)NPAD * 128];
__device__ __align__(16) __half g_s3h [(size_t)NPAD * 32];

// Per-block edge-dtype detection: sample high words of the first 64 int64 slots.
// int64 node-ids < 2^31 have all-zero high words; 64 random int32 ids are all
// zero with P ~ 1e-320. Deterministic (same data every run).
#define DETECT_IS64(w32, is64_var)                                   \
    __shared__ int s_any;                                            \
    if (threadIdx.x == 0) s_any = 0;                                 \
    __syncthreads();                                                 \
    if (threadIdx.x < 64 && (w32)[2 * threadIdx.x + 1] != 0)         \
        atomicOr(&s_any, 1);                                         \
    __syncthreads();                                                 \
    const bool is64_var = (s_any == 0);

__device__ __forceinline__ int edge_at(const void* ed, bool is64, size_t idx) {
    return is64 ? (int)((const long long*)ed)[idx] : ((const int*)ed)[idx];
}

// ---- fused prep: convert x->fp16 AND count in-degrees (g_cnt pre-zeroed) ----
__global__ void prep_count(const float* __restrict__ x, const void* __restrict__ ed,
                           int N, int E) {
    DETECT_IS64((const int*)ed, is64);
    int i = blockIdx.x * blockDim.x + threadIdx.x;
    if (i < N * 32) g_xh[i] = __float2half(x[i]);
    if (i < E) {
        int d = edge_at(ed, is64, (size_t)E + i);
        if ((unsigned)d < (unsigned)N) atomicAdd(&g_cnt[d], 1);
    }
}

// ---- scan pass 1 (+ dis/fill init) ----
__global__ void scan_reduce(int N) {
    __shared__ int sm[1024];
    int idx = blockIdx.x * 1024 + threadIdx.x;
    int c = (idx < N) ? g_cnt[idx] : 0;
    sm[threadIdx.x] = c;
    if (idx < N) { g_dis[idx] = rsqrtf((float)(c + 1)); g_fill[idx] = 0; }
    __syncthreads();
    for (int s = 512; s > 0; s >>= 1) {
        if (threadIdx.x < s) sm[threadIdx.x] += sm[threadIdx.x + s];
        __syncthreads();
    }
    if (threadIdx.x == 0) g_bsum[blockIdx.x] = sm[0];
}

// ---- parallel top-level scan over nb (<=128) block sums ----
__global__ void scan_top(int nb, int N) {
    __shared__ int sm[128];
    int t = threadIdx.x;
    int v = (t < nb) ? g_bsum[t] : 0;
    sm[t] = v;
    __syncthreads();
    for (int off = 1; off < 128; off <<= 1) {
        int u = (t >= off) ? sm[t - off] : 0;
        __syncthreads();
        sm[t] += u;
        __syncthreads();
    }
    if (t < nb) g_bofs[t] = sm[t] - v;          // exclusive
    if (t == nb - 1) g_rowptr[N] = sm[t];       // total
}

// ---- scan pass 2: write exclusive rowptr; zero g_cnt for the next replay ----
__global__ void scan_write(int N) {
    __shared__ int sm[1024];
    int idx = blockIdx.x * 1024 + threadIdx.x;
    int v = (idx < N) ? g_cnt[idx] : 0;
    sm[threadIdx.x] = v;
    __syncthreads();
    for (int off = 1; off < 1024; off <<= 1) {
        int t = (threadIdx.x >= off) ? sm[threadIdx.x - off] : 0;
        __syncthreads();
        sm[threadIdx.x] += t;
        __syncthreads();
    }
    if (idx < N) {
        g_rowptr[idx] = g_bofs[blockIdx.x] + sm[threadIdx.x] - v;
        g_cnt[idx] = 0;                          // ready for next run
    }
}

__global__ void fill_csr(const void* __restrict__ ed, int E, int N) {
    DETECT_IS64((const int*)ed, is64);
    int e = blockIdx.x * blockDim.x + threadIdx.x;
    if (e >= E) return;
    int s = edge_at(ed, is64, e);
    int d = edge_at(ed, is64, (size_t)E + e);
    if ((unsigned)s >= (unsigned)N || (unsigned)d >= (unsigned)N) return;
    int pos = g_rowptr[d] + atomicAdd(&g_fill[d], 1);
    g_colsrc[pos] = s;
}

// ---------------- tensor-core GEMM: Y[N,NOUT] = A[N,K](fp16) @ W(fp32->fp16) ----
template <int K, int NOUT, bool EPI>
__global__ __launch_bounds__(256) void wgemm(
    const __half* __restrict__ A, const float* __restrict__ Wf,
    const float* __restrict__ Bias, __half* __restrict__ Y)
{
    constexpr int WN = (NOUT == 128) ? 2 : 1;
    constexpr int WM = 8 / WN;
    constexpr int NFRAG = NOUT / (WN * 16);
    constexpr int MFRAG = 2;
    constexpr int MBLK = WM * MFRAG * 16;
    constexpr int LDA = K + 8;
    constexpr int LDB = NOUT + 8;
    extern __shared__ __half smh[];
    __half* As = smh;
    __half* Bs = smh + MBLK * LDA;
    const int tid = threadIdx.x;
    const int row0 = blockIdx.x * MBLK;

    for (int i = tid; i < K * NOUT; i += 256) {
        int k = i / NOUT, n = i % NOUT;
        Bs[k * LDB + n] = __float2half(Wf[i]);
    }
    constexpr int CH = K / 8;
    for (int i = tid; i < MBLK * CH; i += 256) {
        int r = i / CH, ch = i % CH;
        uint4 v = *(const uint4*)&A[((size_t)(row0 + r)) * K + ch * 8];
        *(uint4*)&As[r * LDA + ch * 8] = v;
    }
    __syncthreads();

    const int wid = tid >> 5;
    const int wm = wid % WM, wn = wid / WM;
    const int mrow = wm * MFRAG * 16;
    const int ncol = wn * NFRAG * 16;

    wmma::fragment<wmma::accumulator, 16, 16, 16, float> acc[MFRAG][NFRAG];
#pragma unroll
    for (int m = 0; m < MFRAG; m++)
#pragma unroll
        for (int n = 0; n < NFRAG; n++) wmma::fill_fragment(acc[m][n], 0.f);

#pragma unroll
    for (int k = 0; k < K; k += 16) {
        wmma::fragment<wmma::matrix_a, 16, 16, 16, __half, wmma::row_major> af[MFRAG];
#pragma unroll
        for (int m = 0; m < MFRAG; m++)
            wmma::load_matrix_sync(af[m], As + (mrow + m * 16) * LDA + k, LDA);
        wmma::fragment<wmma::matrix_b, 16, 16, 16, __half, wmma::row_major> bf[NFRAG];
#pragma unroll
        for (int n = 0; n < NFRAG; n++)
            wmma::load_matrix_sync(bf[n], Bs + k * LDB + ncol + n * 16, LDB);
#pragma unroll
        for (int m = 0; m < MFRAG; m++)
#pragma unroll
            for (int n = 0; n < NFRAG; n++)
                wmma::mma_sync(acc[m][n], af[m], bf[n], acc[m][n]);
    }
    __syncthreads();

    float* stage = (float*)smh + wid * 272;
    const int lane = tid & 31;
    const int r = lane >> 1, c0 = (lane & 1) * 8;
#pragma unroll
    for (int m = 0; m < MFRAG; m++)
#pragma unroll
        for (int n = 0; n < NFRAG; n++) {
            wmma::store_matrix_sync(stage, acc[m][n], 16, wmma::mem_row_major);
            __syncwarp();
            int grow = row0 + mrow + m * 16 + r;
            int gcol = ncol + n * 16 + c0;
            __half h[8];
#pragma unroll
            for (int j = 0; j < 8; j++) {
                float v = stage[r * 16 + c0 + j];
                if constexpr (EPI) v = fmaxf(v + Bias[gcol + j], 0.f);
                h[j] = __float2half(v);
            }
            *(uint4*)&Y[(size_t)grow * NOUT + gcol] = *(uint4*)h;
            __syncwarp();
        }
}

// ---------------- agg F=32 ----------------
template <bool EPI, bool OUTF>
__global__ __launch_bounds__(256) void agg32_kernel(
    const __half* __restrict__ H, const float* __restrict__ B,
    __half* __restrict__ outh, float* __restrict__ outf, int N)
{
    int gw = (blockIdx.x * 256 + threadIdx.x) >> 5;
    int lane = threadIdx.x & 31;
    if (gw >= N) return;
    const float di = g_dis[gw];
    const int beg = g_rowptr[gw], end = g_rowptr[gw + 1];

    float acc = di * __half2float(H[(size_t)gw * 32 + lane]);
    int e = beg;
    for (; e + 4 <= end; e += 4) {
        int s0 = g_colsrc[e], s1 = g_colsrc[e + 1];
        int s2 = g_colsrc[e + 2], s3 = g_colsrc[e + 3];
        float w0 = g_dis[s0], w1 = g_dis[s1], w2 = g_dis[s2], w3 = g_dis[s3];
        float v0 = __half2float(H[(size_t)s0 * 32 + lane]);
        float v1 = __half2float(H[(size_t)s1 * 32 + lane]);
        float v2 = __half2float(H[(size_t)s2 * 32 + lane]);
        float v3 = __half2float(H[(size_t)s3 * 32 + lane]);
        acc = fmaf(w0, v0, acc);
        acc = fmaf(w1, v1, acc);
        acc = fmaf(w2, v2, acc);
        acc = fmaf(w3, v3, acc);
    }
    for (; e < end; e++) {
        int s = g_colsrc[e];
        acc = fmaf(g_dis[s], __half2float(H[(size_t)s * 32 + lane]), acc);
    }
    acc *= di;
    if constexpr (EPI) acc = fmaxf(acc + B[lane], 0.f);
    if constexpr (OUTF) outf[(size_t)gw * 32 + lane] = acc;
    else               outh[(size_t)gw * 32 + lane] = __float2half(acc);
}

// ---------------- agg F=128 ----------------
__device__ __forceinline__ float4 h4_to_f4(uint2 v) {
    __half2 a = *(__half2*)&v.x, b = *(__half2*)&v.y;
    float2 fa = __half22float2(a), fb = __half22float2(b);
    return make_float4(fa.x, fa.y, fb.x, fb.y);
}

__global__ __launch_bounds__(256) void agg128h_kernel(
    const __half* __restrict__ H, __half* __restrict__ out, int N)
{
    int gw = (blockIdx.x * 256 + threadIdx.x) >> 5;
    int lane = threadIdx.x & 31;
    if (gw >= N) return;
    const float di = g_dis[gw];
    const int beg = g_rowptr[gw], end = g_rowptr[gw + 1];

    float4 h0 = h4_to_f4(((const uint2*)(H + (size_t)gw * 128))[lane]);
    float4 acc = make_float4(di * h0.x, di * h0.y, di * h0.z, di * h0.w);
    int e = beg;
    for (; e + 4 <= end; e += 4) {
        int s0 = g_colsrc[e], s1 = g_colsrc[e + 1];
        int s2 = g_colsrc[e + 2], s3 = g_colsrc[e + 3];
        float w0 = g_dis[s0], w1 = g_dis[s1], w2 = g_dis[s2], w3 = g_dis[s3];
        float4 v0 = h4_to_f4(((const uint2*)(H + (size_t)s0 * 128))[lane]);
        float4 v1 = h4_to_f4(((const uint2*)(H + (size_t)s1 * 128))[lane]);
        float4 v2 = h4_to_f4(((const uint2*)(H + (size_t)s2 * 128))[lane]);
        float4 v3 = h4_to_f4(((const uint2*)(H + (size_t)s3 * 128))[lane]);
        acc.x = fmaf(w0, v0.x, acc.x); acc.y = fmaf(w0, v0.y, acc.y);
        acc.z = fmaf(w0, v0.z, acc.z); acc.w = fmaf(w0, v0.w, acc.w);
        acc.x = fmaf(w1, v1.x, acc.x); acc.y = fmaf(w1, v1.y, acc.y);
        acc.z = fmaf(w1, v1.z, acc.z); acc.w = fmaf(w1, v1.w, acc.w);
        acc.x = fmaf(w2, v2.x, acc.x); acc.y = fmaf(w2, v2.y, acc.y);
        acc.z = fmaf(w2, v2.z, acc.z); acc.w = fmaf(w2, v2.w, acc.w);
        acc.x = fmaf(w3, v3.x, acc.x); acc.y = fmaf(w3, v3.y, acc.y);
        acc.z = fmaf(w3, v3.z, acc.z); acc.w = fmaf(w3, v3.w, acc.w);
    }
    for (; e < end; e++) {
        int s = g_colsrc[e];
        float w = g_dis[s];
        float4 v = h4_to_f4(((const uint2*)(H + (size_t)s * 128))[lane]);
        acc.x = fmaf(w, v.x, acc.x); acc.y = fmaf(w, v.y, acc.y);
        acc.z = fmaf(w, v.z, acc.z); acc.w = fmaf(w, v.w, acc.w);
    }
    __half2 o01 = __floats2half2_rn(di * acc.x, di * acc.y);
    __half2 o23 = __floats2half2_rn(di * acc.z, di * acc.w);
    uint2 pk = make_uint2(*(unsigned*)&o01, *(unsigned*)&o23);
    ((uint2*)(out + (size_t)gw * 128))[lane] = pk;
}

extern "C" void kernel_launch(void* const* d_in, const int* in_sizes, int n_in,
                              void* d_out, int out_size) {
    const float* x  = (const float*)d_in[0];
    const void*  ed = d_in[1];
    const float* W1 = (const float*)d_in[2];
    const float* b1 = (const float*)d_in[3];
    const float* W2 = (const float*)d_in[4];
    const float* b2 = (const float*)d_in[5];
    const float* W3 = (const float*)d_in[6];
    const float* b3 = (const float*)d_in[7];
    float* out = (float*)d_out;

    const int N = in_sizes[0] / 32;
    const int E = in_sizes[1] / 2;
    const int nb = (N + 1023) / 1024;

    __half *xh, *s32h, *h16, *hB, *hA, *s3h;
    cudaGetSymbolAddress((void**)&xh,   g_xh);
    cudaGetSymbolAddress((void**)&s32h, g_s32h);
    cudaGetSymbolAddress((void**)&h16,  g_h16);
    cudaGetSymbolAddress((void**)&hB,   g_hB);
    cudaGetSymbolAddress((void**)&hA,   g_hA);
    cudaGetSymbolAddress((void**)&s3h,  g_s3h);

    const int eblk = (E + 255) / 256;
    const int ablk = (N * 32 + 255) / 256;
    const int pblk = (N * 32 + 255) / 256;

    const int sm1 = (128 * 40 + 32 * 136) * 2;
    const int sm2 = (128 * 136 + 128 * 136) * 2;
    const int sm3 = (256 * 136 + 128 * 40) * 2;
    cudaFuncSetAttribute(wgemm<32, 128, true>,  cudaFuncAttributeMaxDynamicSharedMemorySize, sm1);
    cudaFuncSetAttribute(wgemm<128, 128, true>, cudaFuncAttributeMaxDynamicSharedMemorySize, sm2);
    cudaFuncSetAttribute(wgemm<128, 32, false>, cudaFuncAttributeMaxDynamicSharedMemorySize, sm3);

    // CSR + norm build (5 launches)
    prep_count<<<pblk, 256>>>(x, ed, N, E);
    scan_reduce<<<nb, 1024>>>(N);
    scan_top<<<1, 128>>>(nb, N);
    scan_write<<<nb, 1024>>>(N);
    fill_csr<<<eblk, 256>>>(ed, E, N);

    // L1: relu(Agg(x) @ W1 + b1)
    agg32_kernel<false, false><<<ablk, 256>>>(xh, nullptr, s32h, nullptr, N);
    wgemm<32, 128, true><<<(N + 127) / 128, 256, sm1>>>(s32h, W1, b1, h16);

    // L2: relu(Agg(h1) @ W2 + b2)
    agg128h_kernel<<<ablk, 256>>>(h16, hB, N);
    wgemm<128, 128, true><<<(N + 127) / 128, 256, sm2>>>(hB, W2, b2, hA);

    // L3: relu(Agg(h2 @ W3) + b3)
    wgemm<128, 32, false><<<(N + 255) / 256, 256, sm3>>>(hA, W3, nullptr, s3h);
    agg32_kernel<true, true><<<ablk, 256>>>(s3h, b3, nullptr, out, N);
}

// round 13
// speedup vs baseline: 1.2264x; 1.0522x over previous
#include <cuda_runtime.h>
#include <cuda_fp16.h>
#include <mma.h>
#include <cstdint>
using namespace nvcuda;

#define N_NODES 100000
#define N_EDGES 1600000
#define NPAD    100352   // multiple of 256

__device__ int   g_cnt[N_NODES];     // zero at module load; re-zeroed in scan_write each run
__device__ int   g_fill[N_NODES];
__device__ float g_dis[N_NODES];
__device__ int   g_rowptr[N_NODES + 1];
__device__ int   g_bsum[256];
__device__ int   g_colsrc[N_EDGES];
__device__ __align__(16) __half g_xh  [(size_t)NPAD * 32];
__device__ __align__(16) __half g_s32h[(size_t)NPAD * 32];
__device__ __align__(16) __half g_h16 [(size_t)NPAD * 128];
__device__ __align__(16) __half g_hB  [(size_t)NPAD * 128];
__device__ __align__(16) __half g_hA  [(size_t)NPAD * 128];
__device__ __align__(16) __half g_s3h [(size_t)NPAD * 32];

// Per-block edge-dtype detection: sample high words of the first 64 int64 slots.
#define DETECT_IS64(w32, is64_var)                                   \
    __shared__ int s_any;                                            \
    if (threadIdx.x == 0) s_any = 0;                                 \
    __syncthreads();                                                 \
    if (threadIdx.x < 64 && (w32)[2 * threadIdx.x + 1] != 0)         \
        atomicOr(&s_any, 1);                                         \
    __syncthreads();                                                 \
    const bool is64_var = (s_any == 0);

__device__ __forceinline__ int edge_at(const void* ed, bool is64, size_t idx) {
    return is64 ? (int)((const long long*)ed)[idx] : ((const int*)ed)[idx];
}

// ---- fused prep: vectorized x->fp16 convert AND in-degree count ----
__global__ void prep_count(const float* __restrict__ x, const void* __restrict__ ed,
                           int N, int E) {
    DETECT_IS64((const int*)ed, is64);
    int i = blockIdx.x * blockDim.x + threadIdx.x;
    int nq = N * 8;                       // 4 floats per thread
    if (i < nq) {
        float4 f = ((const float4*)x)[i];
        __half2 a = __floats2half2_rn(f.x, f.y);
        __half2 b = __floats2half2_rn(f.z, f.w);
        ((uint2*)g_xh)[i] = make_uint2(*(unsigned*)&a, *(unsigned*)&b);
    }
    if (i < E) {
        int d = edge_at(ed, is64, (size_t)E + i);
        if ((unsigned)d < (unsigned)N) atomicAdd(&g_cnt[d], 1);
    }
}

// ---- scan pass 1 (+ dis/fill init) ----
__global__ void scan_reduce(int N) {
    __shared__ int sm[1024];
    int idx = blockIdx.x * 1024 + threadIdx.x;
    int c = (idx < N) ? g_cnt[idx] : 0;
    sm[threadIdx.x] = c;
    if (idx < N) { g_dis[idx] = rsqrtf((float)(c + 1)); g_fill[idx] = 0; }
    __syncthreads();
    for (int s = 512; s > 0; s >>= 1) {
        if (threadIdx.x < s) sm[threadIdx.x] += sm[threadIdx.x + s];
        __syncthreads();
    }
    if (threadIdx.x == 0) g_bsum[blockIdx.x] = sm[0];
}

// ---- scan pass 2: per-block top-level re-scan + exclusive rowptr; re-zero cnt ----
__global__ __launch_bounds__(1024) void scan_write(int N, int nb) {
    __shared__ int sm[1024];
    __shared__ int top[128];
    const int tid = threadIdx.x;
    const int idx = blockIdx.x * 1024 + tid;
    int v = (idx < N) ? g_cnt[idx] : 0;
    sm[tid] = v;
    if (tid < 128) top[tid] = (tid < nb) ? g_bsum[tid] : 0;
    __syncthreads();
    // inclusive scan of the <=128 block sums (all threads hit barriers)
    for (int off = 1; off < 128; off <<= 1) {
        int t = (tid >= off && tid < 128) ? top[tid - off] : 0;
        __syncthreads();
        if (tid < 128) top[tid] += t;
        __syncthreads();
    }
    // inclusive scan within the tile
    for (int off = 1; off < 1024; off <<= 1) {
        int t = (tid >= off) ? sm[tid - off] : 0;
        __syncthreads();
        sm[tid] += t;
        __syncthreads();
    }
    const int excl_top = top[blockIdx.x] - g_bsum[blockIdx.x];
    if (idx < N) {
        g_rowptr[idx] = excl_top + sm[tid] - v;   // exclusive
        g_cnt[idx] = 0;                           // ready for next replay
    }
    if (blockIdx.x == nb - 1 && tid == 0) g_rowptr[N] = top[nb - 1];
}

__global__ void fill_csr(const void* __restrict__ ed, int E, int N) {
    DETECT_IS64((const int*)ed, is64);
    int e = blockIdx.x * blockDim.x + threadIdx.x;
    if (e >= E) return;
    int s = edge_at(ed, is64, e);
    int d = edge_at(ed, is64, (size_t)E + e);
    if ((unsigned)s >= (unsigned)N || (unsigned)d >= (unsigned)N) return;
    int pos = g_rowptr[d] + atomicAdd(&g_fill[d], 1);
    g_colsrc[pos] = s;
}

// ---------------- tensor-core GEMM: Y[N,NOUT] = A[N,K](fp16) @ W(fp32->fp16) ----
template <int K, int NOUT, bool EPI>
__global__ __launch_bounds__(256) void wgemm(
    const __half* __restrict__ A, const float* __restrict__ Wf,
    const float* __restrict__ Bias, __half* __restrict__ Y)
{
    constexpr int WN = (NOUT == 128) ? 2 : 1;
    constexpr int WM = 8 / WN;
    constexpr int NFRAG = NOUT / (WN * 16);
    constexpr int MFRAG = 2;
    constexpr int MBLK = WM * MFRAG * 16;
    constexpr int LDA = K + 8;
    constexpr int LDB = NOUT + 8;
    extern __shared__ __half smh[];
    __half* As = smh;
    __half* Bs = smh + MBLK * LDA;
    const int tid = threadIdx.x;
    const int row0 = blockIdx.x * MBLK;

    for (int i = tid; i < K * NOUT; i += 256) {
        int k = i / NOUT, n = i % NOUT;
        Bs[k * LDB + n] = __float2half(Wf[i]);
    }
    constexpr int CH = K / 8;
    for (int i = tid; i < MBLK * CH; i += 256) {
        int r = i / CH, ch = i % CH;
        uint4 v = *(const uint4*)&A[((size_t)(row0 + r)) * K + ch * 8];
        *(uint4*)&As[r * LDA + ch * 8] = v;
    }
    __syncthreads();

    const int wid = tid >> 5;
    const int wm = wid % WM, wn = wid / WM;
    const int mrow = wm * MFRAG * 16;
    const int ncol = wn * NFRAG * 16;

    wmma::fragment<wmma::accumulator, 16, 16, 16, float> acc[MFRAG][NFRAG];
#pragma unroll
    for (int m = 0; m < MFRAG; m++)
#pragma unroll
        for (int n = 0; n < NFRAG; n++) wmma::fill_fragment(acc[m][n], 0.f);

#pragma unroll
    for (int k = 0; k < K; k += 16) {
        wmma::fragment<wmma::matrix_a, 16, 16, 16, __half, wmma::row_major> af[MFRAG];
#pragma unroll
        for (int m = 0; m < MFRAG; m++)
            wmma::load_matrix_sync(af[m], As + (mrow + m * 16) * LDA + k, LDA);
        wmma::fragment<wmma::matrix_b, 16, 16, 16, __half, wmma::row_major> bf[NFRAG];
#pragma unroll
        for (int n = 0; n < NFRAG; n++)
            wmma::load_matrix_sync(bf[n], Bs + k * LDB + ncol + n * 16, LDB);
#pragma unroll
        for (int m = 0; m < MFRAG; m++)
#pragma unroll
            for (int n = 0; n < NFRAG; n++)
                wmma::mma_sync(acc[m][n], af[m], bf[n], acc[m][n]);
    }
    __syncthreads();

    float* stage = (float*)smh + wid * 272;
    const int lane = tid & 31;
    const int r = lane >> 1, c0 = (lane & 1) * 8;
#pragma unroll
    for (int m = 0; m < MFRAG; m++)
#pragma unroll
        for (int n = 0; n < NFRAG; n++) {
            wmma::store_matrix_sync(stage, acc[m][n], 16, wmma::mem_row_major);
            __syncwarp();
            int grow = row0 + mrow + m * 16 + r;
            int gcol = ncol + n * 16 + c0;
            __half h[8];
#pragma unroll
            for (int j = 0; j < 8; j++) {
                float v = stage[r * 16 + c0 + j];
                if constexpr (EPI) v = fmaxf(v + Bias[gcol + j], 0.f);
                h[j] = __float2half(v);
            }
            *(uint4*)&Y[(size_t)grow * NOUT + gcol] = *(uint4*)h;
            __syncwarp();
        }
}

// ---------------- agg F=32, unroll 8 ----------------
template <bool EPI, bool OUTF>
__global__ __launch_bounds__(256) void agg32_kernel(
    const __half* __restrict__ H, const float* __restrict__ B,
    __half* __restrict__ outh, float* __restrict__ outf, int N)
{
    int gw = (blockIdx.x * 256 + threadIdx.x) >> 5;
    int lane = threadIdx.x & 31;
    if (gw >= N) return;
    const float di = g_dis[gw];
    const int beg = g_rowptr[gw], end = g_rowptr[gw + 1];

    float acc = di * __half2float(H[(size_t)gw * 32 + lane]);
    int e = beg;
    for (; e + 8 <= end; e += 8) {
        int s[8];
#pragma unroll
        for (int j = 0; j < 8; j++) s[j] = g_colsrc[e + j];
        float w[8];
#pragma unroll
        for (int j = 0; j < 8; j++) w[j] = g_dis[s[j]];
        float v[8];
#pragma unroll
        for (int j = 0; j < 8; j++) v[j] = __half2float(H[(size_t)s[j] * 32 + lane]);
#pragma unroll
        for (int j = 0; j < 8; j++) acc = fmaf(w[j], v[j], acc);
    }
    for (; e < end; e++) {
        int s = g_colsrc[e];
        acc = fmaf(g_dis[s], __half2float(H[(size_t)s * 32 + lane]), acc);
    }
    acc *= di;
    if constexpr (EPI) acc = fmaxf(acc + B[lane], 0.f);
    if constexpr (OUTF) outf[(size_t)gw * 32 + lane] = acc;
    else               outh[(size_t)gw * 32 + lane] = __float2half(acc);
}

// ---------------- agg F=128, unroll 8 ----------------
__device__ __forceinline__ float4 h4_to_f4(uint2 v) {
    __half2 a = *(__half2*)&v.x, b = *(__half2*)&v.y;
    float2 fa = __half22float2(a), fb = __half22float2(b);
    return make_float4(fa.x, fa.y, fb.x, fb.y);
}

__global__ __launch_bounds__(256) void agg128h_kernel(
    const __half* __restrict__ H, __half* __restrict__ out, int N)
{
    int gw = (blockIdx.x * 256 + threadIdx.x) >> 5;
    int lane = threadIdx.x & 31;
    if (gw >= N) return;
    const float di = g_dis[gw];
    const int beg = g_rowptr[gw], end = g_rowptr[gw + 1];

    float4 h0 = h4_to_f4(((const uint2*)(H + (size_t)gw * 128))[lane]);
    float4 acc = make_float4(di * h0.x, di * h0.y, di * h0.z, di * h0.w);
    int e = beg;
    for (; e + 8 <= end; e += 8) {
        int s[8];
#pragma unroll
        for (int j = 0; j < 8; j++) s[j] = g_colsrc[e + j];
        float w[8];
#pragma unroll
        for (int j = 0; j < 8; j++) w[j] = g_dis[s[j]];
        uint2 raw[8];
#pragma unroll
        for (int j = 0; j < 8; j++) raw[j] = ((const uint2*)(H + (size_t)s[j] * 128))[lane];
#pragma unroll
        for (int j = 0; j < 8; j++) {
            float4 v = h4_to_f4(raw[j]);
            acc.x = fmaf(w[j], v.x, acc.x); acc.y = fmaf(w[j], v.y, acc.y);
            acc.z = fmaf(w[j], v.z, acc.z); acc.w = fmaf(w[j], v.w, acc.w);
        }
    }
    for (; e < end; e++) {
        int s = g_colsrc[e];
        float w = g_dis[s];
        float4 v = h4_to_f4(((const uint2*)(H + (size_t)s * 128))[lane]);
        acc.x = fmaf(w, v.x, acc.x); acc.y = fmaf(w, v.y, acc.y);
        acc.z = fmaf(w, v.z, acc.z); acc.w = fmaf(w, v.w, acc.w);
    }
    __half2 o01 = __floats2half2_rn(di * acc.x, di * acc.y);
    __half2 o23 = __floats2half2_rn(di * acc.z, di * acc.w);
    uint2 pk = make_uint2(*(unsigned*)&o01, *(unsigned*)&o23);
    ((uint2*)(out + (size_t)gw * 128))[lane] = pk;
}

extern "C" void kernel_launch(void* const* d_in, const int* in_sizes, int n_in,
                              void* d_out, int out_size) {
    const float* x  = (const float*)d_in[0];
    const void*  ed = d_in[1];
    const float* W1 = (const float*)d_in[2];
    const float* b1 = (const float*)d_in[3];
    const float* W2 = (const float*)d_in[4];
    const float* b2 = (const float*)d_in[5];
    const float* W3 = (const float*)d_in[6];
    const float* b3 = (const float*)d_in[7];
    float* out = (float*)d_out;

    const int N = in_sizes[0] / 32;
    const int E = in_sizes[1] / 2;
    const int nb = (N + 1023) / 1024;

    __half *xh, *s32h, *h16, *hB, *hA, *s3h;
    cudaGetSymbolAddress((void**)&xh,   g_xh);
    cudaGetSymbolAddress((void**)&s32h, g_s32h);
    cudaGetSymbolAddress((void**)&h16,  g_h16);
    cudaGetSymbolAddress((void**)&hB,   g_hB);
    cudaGetSymbolAddress((void**)&hA,   g_hA);
    cudaGetSymbolAddress((void**)&s3h,  g_s3h);

    const int eblk = (E + 255) / 256;
    const int ablk = (N * 32 + 255) / 256;
    const int pwork = (N * 8 > E) ? N * 8 : E;
    const int pblk = (pwork + 255) / 256;

    const int sm1 = (128 * 40 + 32 * 136) * 2;
    const int sm2 = (128 * 136 + 128 * 136) * 2;
    const int sm3 = (256 * 136 + 128 * 40) * 2;
    cudaFuncSetAttribute(wgemm<32, 128, true>,  cudaFuncAttributeMaxDynamicSharedMemorySize, sm1);
    cudaFuncSetAttribute(wgemm<128, 128, true>, cudaFuncAttributeMaxDynamicSharedMemorySize, sm2);
    cudaFuncSetAttribute(wgemm<128, 32, false>, cudaFuncAttributeMaxDynamicSharedMemorySize, sm3);

    // CSR + norm build (4 launches)
    prep_count<<<pblk, 256>>>(x, ed, N, E);
    scan_reduce<<<nb, 1024>>>(N);
    scan_write<<<nb, 1024>>>(N, nb);
    fill_csr<<<eblk, 256>>>(ed, E, N);

    // L1: relu(Agg(x) @ W1 + b1)
    agg32_kernel<false, false><<<ablk, 256>>>(xh, nullptr, s32h, nullptr, N);
    wgemm<32, 128, true><<<(N + 127) / 128, 256, sm1>>>(s32h, W1, b1, h16);

    // L2: relu(Agg(h1) @ W2 + b2)
    agg128h_kernel<<<ablk, 256>>>(h16, hB, N);
    wgemm<128, 128, true><<<(N + 127) / 128, 256, sm2>>>(hB, W2, b2, hA);

    // L3: relu(Agg(h2 @ W3) + b3)
    wgemm<128, 32, false><<<(N + 255) / 256, 256, sm3>>>(hA, W3, nullptr, s3h);
    agg32_kernel<true, true><<<ablk, 256>>>(s3h, b3, nullptr, out, N);
}

// round 14
// speedup vs baseline: 1.3164x; 1.0734x over previous
#include <cuda_runtime.h>
#include <cuda_fp16.h>
#include <mma.h>
#include <cstdint>
using namespace nvcuda;

#define N_NODES 100000
#define N_EDGES 1600000
#define NPAD    100352   // multiple of 256

__device__ int   g_cnt[N_NODES];     // zero at module load; re-zeroed in scan_write each run
__device__ int   g_fill[N_NODES];
__device__ float g_dis[N_NODES];
__device__ int   g_rowptr[N_NODES + 1];
__device__ int   g_bsum[256];
__device__ int   g_colsrc[N_EDGES];
__device__ __align__(16) __half g_xh  [(size_t)NPAD * 32];   // dis*x (pre-scaled)
__device__ __align__(16) __half g_s32h[(size_t)NPAD * 32];
__device__ __align__(16) __half g_h16 [(size_t)NPAD * 128];  // dis*h1 (pre-scaled)
__device__ __align__(16) __half g_hB  [(size_t)NPAD * 128];
__device__ __align__(16) __half g_hA  [(size_t)NPAD * 128];
__device__ __align__(16) __half g_s3h [(size_t)NPAD * 32];   // dis*(h2@W3) (pre-scaled)

// Per-block edge-dtype detection: sample high words of the first 64 int64 slots.
#define DETECT_IS64(w32, is64_var)                                   \
    __shared__ int s_any;                                            \
    if (threadIdx.x == 0) s_any = 0;                                 \
    __syncthreads();                                                 \
    if (threadIdx.x < 64 && (w32)[2 * threadIdx.x + 1] != 0)         \
        atomicOr(&s_any, 1);                                         \
    __syncthreads();                                                 \
    const bool is64_var = (s_any == 0);

__device__ __forceinline__ int edge_at(const void* ed, bool is64, size_t idx) {
    return is64 ? (int)((const long long*)ed)[idx] : ((const int*)ed)[idx];
}

// ---- count in-degrees ----
__global__ void prep_count(const void* __restrict__ ed, int N, int E) {
    DETECT_IS64((const int*)ed, is64);
    int i = blockIdx.x * blockDim.x + threadIdx.x;
    if (i < E) {
        int d = edge_at(ed, is64, (size_t)E + i);
        if ((unsigned)d < (unsigned)N) atomicAdd(&g_cnt[d], 1);
    }
}

// ---- scan pass 1 (+ dis/fill init) ----
__global__ void scan_reduce(int N) {
    __shared__ int sm[1024];
    int idx = blockIdx.x * 1024 + threadIdx.x;
    int c = (idx < N) ? g_cnt[idx] : 0;
    sm[threadIdx.x] = c;
    if (idx < N) { g_dis[idx] = rsqrtf((float)(c + 1)); g_fill[idx] = 0; }
    __syncthreads();
    for (int s = 512; s > 0; s >>= 1) {
        if (threadIdx.x < s) sm[threadIdx.x] += sm[threadIdx.x + s];
        __syncthreads();
    }
    if (threadIdx.x == 0) g_bsum[blockIdx.x] = sm[0];
}

// ---- scan pass 2: per-block top-level re-scan + exclusive rowptr; re-zero cnt ----
__global__ __launch_bounds__(1024) void scan_write(int N, int nb) {
    __shared__ int sm[1024];
    __shared__ int top[128];
    const int tid = threadIdx.x;
    const int idx = blockIdx.x * 1024 + tid;
    int v = (idx < N) ? g_cnt[idx] : 0;
    sm[tid] = v;
    if (tid < 128) top[tid] = (tid < nb) ? g_bsum[tid] : 0;
    __syncthreads();
    for (int off = 1; off < 128; off <<= 1) {
        int t = (tid >= off && tid < 128) ? top[tid - off] : 0;
        __syncthreads();
        if (tid < 128) top[tid] += t;
        __syncthreads();
    }
    for (int off = 1; off < 1024; off <<= 1) {
        int t = (tid >= off) ? sm[tid - off] : 0;
        __syncthreads();
        sm[tid] += t;
        __syncthreads();
    }
    const int excl_top = top[blockIdx.x] - g_bsum[blockIdx.x];
    if (idx < N) {
        g_rowptr[idx] = excl_top + sm[tid] - v;   // exclusive
        g_cnt[idx] = 0;                           // ready for next replay
    }
    if (blockIdx.x == nb - 1 && tid == 0) g_rowptr[N] = top[nb - 1];
}

// ---- fill CSR + fused scaled x->fp16 convert (dis ready after scan_write) ----
__global__ void fill_csr(const void* __restrict__ ed, const float* __restrict__ x,
                         int E, int N) {
    DETECT_IS64((const int*)ed, is64);
    int i = blockIdx.x * blockDim.x + threadIdx.x;
    if (i < N * 8) {                      // 4 floats per thread, scaled by dis[row]
        float4 f = ((const float4*)x)[i];
        float d = g_dis[i >> 3];
        __half2 a = __floats2half2_rn(d * f.x, d * f.y);
        __half2 b = __floats2half2_rn(d * f.z, d * f.w);
        ((uint2*)g_xh)[i] = make_uint2(*(unsigned*)&a, *(unsigned*)&b);
    }
    if (i < E) {
        int s = edge_at(ed, is64, i);
        int d = edge_at(ed, is64, (size_t)E + i);
        if ((unsigned)s < (unsigned)N && (unsigned)d < (unsigned)N) {
            int pos = g_rowptr[d] + atomicAdd(&g_fill[d], 1);
            g_colsrc[pos] = s;
        }
    }
}

// ---------------- tensor-core GEMM: Y[N,NOUT] = A[N,K](fp16) @ W(fp32->fp16) ----
// EPI: +bias, relu.  SCALE: multiply output row by g_dis[row] (pre-scaling for agg).
template <int K, int NOUT, bool EPI, bool SCALE>
__global__ __launch_bounds__(256) void wgemm(
    const __half* __restrict__ A, const float* __restrict__ Wf,
    const float* __restrict__ Bias, __half* __restrict__ Y)
{
    constexpr int WN = (NOUT == 128) ? 2 : 1;
    constexpr int WM = 8 / WN;
    constexpr int NFRAG = NOUT / (WN * 16);
    constexpr int MFRAG = 2;
    constexpr int MBLK = WM * MFRAG * 16;
    constexpr int LDA = K + 8;
    constexpr int LDB = NOUT + 8;
    extern __shared__ __half smh[];
    __half* As = smh;
    __half* Bs = smh + MBLK * LDA;
    const int tid = threadIdx.x;
    const int row0 = blockIdx.x * MBLK;

    for (int i = tid; i < K * NOUT; i += 256) {
        int k = i / NOUT, n = i % NOUT;
        Bs[k * LDB + n] = __float2half(Wf[i]);
    }
    constexpr int CH = K / 8;
    for (int i = tid; i < MBLK * CH; i += 256) {
        int r = i / CH, ch = i % CH;
        uint4 v = *(const uint4*)&A[((size_t)(row0 + r)) * K + ch * 8];
        *(uint4*)&As[r * LDA + ch * 8] = v;
    }
    __syncthreads();

    const int wid = tid >> 5;
    const int wm = wid % WM, wn = wid / WM;
    const int mrow = wm * MFRAG * 16;
    const int ncol = wn * NFRAG * 16;

    wmma::fragment<wmma::accumulator, 16, 16, 16, float> acc[MFRAG][NFRAG];
#pragma unroll
    for (int m = 0; m < MFRAG; m++)
#pragma unroll
        for (int n = 0; n < NFRAG; n++) wmma::fill_fragment(acc[m][n], 0.f);

#pragma unroll
    for (int k = 0; k < K; k += 16) {
        wmma::fragment<wmma::matrix_a, 16, 16, 16, __half, wmma::row_major> af[MFRAG];
#pragma unroll
        for (int m = 0; m < MFRAG; m++)
            wmma::load_matrix_sync(af[m], As + (mrow + m * 16) * LDA + k, LDA);
        wmma::fragment<wmma::matrix_b, 16, 16, 16, __half, wmma::row_major> bf[NFRAG];
#pragma unroll
        for (int n = 0; n < NFRAG; n++)
            wmma::load_matrix_sync(bf[n], Bs + k * LDB + ncol + n * 16, LDB);
#pragma unroll
        for (int m = 0; m < MFRAG; m++)
#pragma unroll
            for (int n = 0; n < NFRAG; n++)
                wmma::mma_sync(acc[m][n], af[m], bf[n], acc[m][n]);
    }
    __syncthreads();

    float* stage = (float*)smh + wid * 272;
    const int lane = tid & 31;
    const int r = lane >> 1, c0 = (lane & 1) * 8;
#pragma unroll
    for (int m = 0; m < MFRAG; m++)
#pragma unroll
        for (int n = 0; n < NFRAG; n++) {
            wmma::store_matrix_sync(stage, acc[m][n], 16, wmma::mem_row_major);
            __syncwarp();
            int grow = row0 + mrow + m * 16 + r;
            int gcol = ncol + n * 16 + c0;
            float ds = 1.f;
            if constexpr (SCALE) ds = (grow < N_NODES) ? g_dis[grow] : 0.f;
            __half h[8];
#pragma unroll
            for (int j = 0; j < 8; j++) {
                float v = stage[r * 16 + c0 + j];
                if constexpr (EPI) v = fmaxf(v + Bias[gcol + j], 0.f);
                if constexpr (SCALE) v *= ds;
                h[j] = __float2half(v);
            }
            *(uint4*)&Y[(size_t)grow * NOUT + gcol] = *(uint4*)h;
            __syncwarp();
        }
}

// ---------------- agg F=32 on pre-scaled G: out = dis_i * (Σ G[s] + G[i]) ----------------
template <bool EPI, bool OUTF>
__global__ __launch_bounds__(256) void agg32_kernel(
    const __half* __restrict__ G, const float* __restrict__ B,
    __half* __restrict__ outh, float* __restrict__ outf, int N)
{
    int gw = (blockIdx.x * 256 + threadIdx.x) >> 5;
    int lane = threadIdx.x & 31;
    if (gw >= N) return;
    const float di = g_dis[gw];
    const int beg = g_rowptr[gw], end = g_rowptr[gw + 1];

    float acc = __half2float(G[(size_t)gw * 32 + lane]);
    int e = beg;
    for (; e + 8 <= end; e += 8) {
        int s[8];
#pragma unroll
        for (int j = 0; j < 8; j++) s[j] = g_colsrc[e + j];
        float v[8];
#pragma unroll
        for (int j = 0; j < 8; j++) v[j] = __half2float(G[(size_t)s[j] * 32 + lane]);
#pragma unroll
        for (int j = 0; j < 8; j++) acc += v[j];
    }
    for (; e < end; e++)
        acc += __half2float(G[(size_t)g_colsrc[e] * 32 + lane]);
    acc *= di;
    if constexpr (EPI) acc = fmaxf(acc + B[lane], 0.f);
    if constexpr (OUTF) outf[(size_t)gw * 32 + lane] = acc;
    else               outh[(size_t)gw * 32 + lane] = __float2half(acc);
}

// ---------------- agg F=128 on pre-scaled G ----------------
__device__ __forceinline__ float4 h4_to_f4(uint2 v) {
    __half2 a = *(__half2*)&v.x, b = *(__half2*)&v.y;
    float2 fa = __half22float2(a), fb = __half22float2(b);
    return make_float4(fa.x, fa.y, fb.x, fb.y);
}

__global__ __launch_bounds__(256) void agg128h_kernel(
    const __half* __restrict__ G, __half* __restrict__ out, int N)
{
    int gw = (blockIdx.x * 256 + threadIdx.x) >> 5;
    int lane = threadIdx.x & 31;
    if (gw >= N) return;
    const float di = g_dis[gw];
    const int beg = g_rowptr[gw], end = g_rowptr[gw + 1];

    float4 acc = h4_to_f4(((const uint2*)(G + (size_t)gw * 128))[lane]);
    int e = beg;
    for (; e + 8 <= end; e += 8) {
        int s[8];
#pragma unroll
        for (int j = 0; j < 8; j++) s[j] = g_colsrc[e + j];
        uint2 raw[8];
#pragma unroll
        for (int j = 0; j < 8; j++) raw[j] = ((const uint2*)(G + (size_t)s[j] * 128))[lane];
#pragma unroll
        for (int j = 0; j < 8; j++) {
            float4 v = h4_to_f4(raw[j]);
            acc.x += v.x; acc.y += v.y; acc.z += v.z; acc.w += v.w;
        }
    }
    for (; e < end; e++) {
        float4 v = h4_to_f4(((const uint2*)(G + (size_t)g_colsrc[e] * 128))[lane]);
        acc.x += v.x; acc.y += v.y; acc.z += v.z; acc.w += v.w;
    }
    __half2 o01 = __floats2half2_rn(di * acc.x, di * acc.y);
    __half2 o23 = __floats2half2_rn(di * acc.z, di * acc.w);
    uint2 pk = make_uint2(*(unsigned*)&o01, *(unsigned*)&o23);
    ((uint2*)(out + (size_t)gw * 128))[lane] = pk;
}

extern "C" void kernel_launch(void* const* d_in, const int* in_sizes, int n_in,
                              void* d_out, int out_size) {
    const float* x  = (const float*)d_in[0];
    const void*  ed = d_in[1];
    const float* W1 = (const float*)d_in[2];
    const float* b1 = (const float*)d_in[3];
    const float* W2 = (const float*)d_in[4];
    const float* b2 = (const float*)d_in[5];
    const float* W3 = (const float*)d_in[6];
    const float* b3 = (const float*)d_in[7];
    float* out = (float*)d_out;

    const int N = in_sizes[0] / 32;
    const int E = in_sizes[1] / 2;
    const int nb = (N + 1023) / 1024;

    __half *xh, *s32h, *h16, *hB, *hA, *s3h;
    cudaGetSymbolAddress((void**)&xh,   g_xh);
    cudaGetSymbolAddress((void**)&s32h, g_s32h);
    cudaGetSymbolAddress((void**)&h16,  g_h16);
    cudaGetSymbolAddress((void**)&hB,   g_hB);
    cudaGetSymbolAddress((void**)&hA,   g_hA);
    cudaGetSymbolAddress((void**)&s3h,  g_s3h);

    const int eblk = (E + 255) / 256;
    const int ablk = (N * 32 + 255) / 256;
    const int fwork = (N * 8 > E) ? N * 8 : E;
    const int fblk = (fwork + 255) / 256;

    const int sm1 = (128 * 40 + 32 * 136) * 2;
    const int sm2 = (128 * 136 + 128 * 136) * 2;
    const int sm3 = (256 * 136 + 128 * 40) * 2;
    cudaFuncSetAttribute(wgemm<32, 128, true, true>,   cudaFuncAttributeMaxDynamicSharedMemorySize, sm1);
    cudaFuncSetAttribute(wgemm<128, 128, true, false>, cudaFuncAttributeMaxDynamicSharedMemorySize, sm2);
    cudaFuncSetAttribute(wgemm<128, 32, false, true>,  cudaFuncAttributeMaxDynamicSharedMemorySize, sm3);

    // CSR + norm build (4 launches); x-convert fused into fill_csr (dis ready there)
    prep_count<<<eblk, 256>>>(ed, N, E);
    scan_reduce<<<nb, 1024>>>(N);
    scan_write<<<nb, 1024>>>(N, nb);
    fill_csr<<<fblk, 256>>>(ed, x, E, N);

    // L1: relu(Agg(x) @ W1 + b1); wgemm writes dis*h1 (pre-scaled for next agg)
    agg32_kernel<false, false><<<ablk, 256>>>(xh, nullptr, s32h, nullptr, N);
    wgemm<32, 128, true, true><<<(N + 127) / 128, 256, sm1>>>(s32h, W1, b1, h16);

    // L2: relu(Agg(h1) @ W2 + b2)
    agg128h_kernel<<<ablk, 256>>>(h16, hB, N);
    wgemm<128, 128, true, false><<<(N + 127) / 128, 256, sm2>>>(hB, W2, b2, hA);

    // L3: relu(Agg(h2 @ W3) + b3); wgemm3 writes dis*(h2@W3)
    wgemm<128, 32, false, true><<<(N + 255) / 256, 256, sm3>>>(hA, W3, nullptr, s3h);
    agg32_kernel<true, true><<<ablk, 256>>>(s3h, b3, nullptr, out, N);
}